// round 15
// baseline (speedup 1.0000x reference)
#include <cuda_runtime.h>
#include <cuda_bf16.h>
#include <cstdint>
#include <math.h>

// ---------------- problem constants ----------------
#define S_    3
#define B_    1024
#define D_    64
#define H_    128
#define O_    128
#define T_    64
#define NROW  3072                    // S_*B_
#define NELEM (NROW * D_)             // 196608
#define RTOL_ 1e-4f
#define ATOL_ 1e-5f
#define MAX_INNER 12

// ---------------- kernel config (round-6 proven) ----------------
#define NCTA 128
#define TPB  128                      // 4 warps
#define NW   4
#define RPW  6                        // rows per warp
#define RPC  24                       // rows per CTA

typedef unsigned long long u64;

// ---------------- packed f32x2 helpers ----------------
__device__ __forceinline__ u64 ffma2(u64 a, u64 b, u64 c) {
    u64 d; asm("fma.rn.f32x2 %0, %1, %2, %3;" : "=l"(d) : "l"(a), "l"(b), "l"(c)); return d;
}
__device__ __forceinline__ u64 dup2(float v) {
    u64 r; asm("mov.b64 %0, {%1, %1};" : "=l"(r) : "f"(v)); return r;
}
__device__ __forceinline__ float2 u2f2(u64 v) {
    float2 f; asm("mov.b64 {%0, %1}, %2;" : "=f"(f.x), "=f"(f.y) : "l"(v)); return f;
}

// fast tanh via MUFU.EX2 + MUFU.RCP: t = (e^{2x}-1)/(e^{2x}+1).
__device__ __forceinline__ float fast_tanh(float x) {
    float xc = fminf(fmaxf(x, -15.f), 15.f);   // overflow guard
    float a = __expf(2.f * xc);
    return __fdividef(a - 1.f, a + 1.f);
}

// ---------------- shared memory layout (round-6 verbatim) ----------------
struct Smem {
    float W1[D_][H_];       // 32 KB
    float W2[H_][D_];       // 32 KB
    float b1[H_];
    float b2[D_];
    float Y [RPC][D_];
    float Y5[RPC][D_];
    float Yt[RPC][D_];
    float Hh[RPC][H_];      // 12 KB
    float K [7][RPC][D_];   // 42 KB
    float red[TPB];
    float s_ratio;
};
#define SMEM_BYTES ((int)sizeof(Smem))

// ---------------- device globals (scratch; no allocations allowed) ----------------
__device__ unsigned g_bar = 0;                         // monotone barrier counter
__device__ float    g_part[2][NCTA];                   // per-CTA partial err sums
__device__ float    g_sol[(size_t)NROW * T_ * D_];     // fallback sol_z scratch

// ---------------- grid-wide barrier (all NCTA CTAs co-resident) ----------------
__device__ __forceinline__ void grid_barrier(int tid) {
    __syncthreads();
    if (tid == 0) {
        __threadfence();
        unsigned arrival = atomicAdd(&g_bar, 1u);
        unsigned target = arrival - (arrival % NCTA) + NCTA;
        while ((int)(*(volatile unsigned*)&g_bar - target) < 0) {
            __nanosleep(64);
        }
        __threadfence();
    }
    __syncthreads();
}

// ---------------- f(Yin) -> Kout : two smem GEMMs, warp-local rows (R14 verbatim) -
// lane l owns cols 4l..4l+3 (stage A) and 2l..2l+1 (stage B).
__device__ __forceinline__ void feval(Smem* s, int w, int l,
                                      const float (*Yin)[D_], float (*Kout)[D_]) {
    __syncwarp();
    const int r0 = w * RPW;

    // ---- stage A: Hh = tanh(Yin @ W1 + b1) ----
    u64 acc0[RPW], acc1[RPW];
    {
        const u64* b1p = (const u64*)s->b1;
        u64 i0 = b1p[2 * l], i1 = b1p[2 * l + 1];
        #pragma unroll
        for (int rr = 0; rr < RPW; rr++) { acc0[rr] = i0; acc1[rr] = i1; }
    }
    #pragma unroll 4
    for (int d0 = 0; d0 < D_; d0 += 4) {
        ulonglong2 wq[4];
        #pragma unroll
        for (int dd = 0; dd < 4; dd++)
            wq[dd] = *(const ulonglong2*)&s->W1[d0 + dd][4 * l];
        float4 yv[RPW];
        #pragma unroll
        for (int rr = 0; rr < RPW; rr++)
            yv[rr] = *(const float4*)&Yin[r0 + rr][d0];        // warp-broadcast, 4 y's
        #pragma unroll
        for (int dd = 0; dd < 4; dd++) {
            #pragma unroll
            for (int rr = 0; rr < RPW; rr++) {
                float y = (dd == 0) ? yv[rr].x : (dd == 1) ? yv[rr].y
                        : (dd == 2) ? yv[rr].z : yv[rr].w;
                u64 yd = dup2(y);
                acc0[rr] = ffma2(yd, wq[dd].x, acc0[rr]);
                acc1[rr] = ffma2(yd, wq[dd].y, acc1[rr]);
            }
        }
    }
    #pragma unroll
    for (int rr = 0; rr < RPW; rr++) {
        float2 p0 = u2f2(acc0[rr]), p1 = u2f2(acc1[rr]);
        float4 hv = make_float4(fast_tanh(p0.x), fast_tanh(p0.y),
                                fast_tanh(p1.x), fast_tanh(p1.y));
        *(float4*)&s->Hh[r0 + rr][4 * l] = hv;
    }
    __syncwarp();

    // ---- stage B: Kout = Hh @ W2 + b2 ----
    u64 a2[RPW];
    {
        u64 ib = ((const u64*)s->b2)[l];
        #pragma unroll
        for (int rr = 0; rr < RPW; rr++) a2[rr] = ib;
    }
    #pragma unroll 4
    for (int j0 = 0; j0 < H_; j0 += 4) {
        u64 w2q[4];
        #pragma unroll
        for (int dd = 0; dd < 4; dd++)
            w2q[dd] = *(const u64*)&s->W2[j0 + dd][2 * l];
        float4 hv[RPW];
        #pragma unroll
        for (int rr = 0; rr < RPW; rr++)
            hv[rr] = *(const float4*)&s->Hh[r0 + rr][j0];      // warp-broadcast, 4 h's
        #pragma unroll
        for (int dd = 0; dd < 4; dd++) {
            #pragma unroll
            for (int rr = 0; rr < RPW; rr++) {
                float h = (dd == 0) ? hv[rr].x : (dd == 1) ? hv[rr].y
                        : (dd == 2) ? hv[rr].z : hv[rr].w;
                a2[rr] = ffma2(dup2(h), w2q[dd], a2[rr]);
            }
        }
    }
    #pragma unroll
    for (int rr = 0; rr < RPW; rr++)
        *(u64*)&Kout[r0 + rr][2 * l] = a2[rr];
    __syncwarp();
}

// ---- Out = Y + dt * sum(cf[kk]*K[kk]), lane-local columns (R6 verbatim) ----
template <int NK>
__device__ __forceinline__ void build_stage(Smem* s, int w, int l, float dtv,
                                            const float* cf, float (*Out)[D_]) {
    const int r0 = w * RPW;
    #pragma unroll
    for (int rr = 0; rr < RPW; rr++) {
        const int r = r0 + rr;
        #pragma unroll
        for (int c = 0; c < 2; c++) {
            const int d = 2 * l + c;
            float acc = 0.f;
            #pragma unroll
            for (int kk = 0; kk < NK; kk++)
                acc = fmaf(cf[kk], s->K[kk][r][d], acc);
            Out[r][d] = fmaf(dtv, acc, s->Y[r][d]);
        }
    }
}

// ---------------- persistent ODE solver kernel ----------------
__global__ void __launch_bounds__(TPB, 1)
ode_kernel(const float* __restrict__ first_point,
           const float* __restrict__ times,
           const float* __restrict__ gW1, const float* __restrict__ gb1,
           const float* __restrict__ gW2, const float* __restrict__ gb2,
           float* __restrict__ sol) {
    extern __shared__ char smem_raw[];
    Smem* s = (Smem*)smem_raw;

    const int tid = threadIdx.x;
    const int w = tid >> 5;
    const int l = tid & 31;
    const int row0 = blockIdx.x * RPC;
    const int r0 = w * RPW;

    // load weights + initial state
    for (int i = tid; i < D_ * H_; i += TPB) ((float*)s->W1)[i] = gW1[i];
    for (int i = tid; i < H_ * D_; i += TPB) ((float*)s->W2)[i] = gW2[i];
    for (int i = tid; i < H_; i += TPB) s->b1[i] = gb1[i];
    for (int i = tid; i < D_; i += TPB) s->b2[i] = gb2[i];
    for (int i = tid; i < RPC * D_; i += TPB)
        ((float*)s->Y)[i] = first_point[(size_t)row0 * D_ + i];
    __syncthreads();

    // sol at t index 0 (coalesced float2)
    #pragma unroll
    for (int rr = 0; rr < RPW; rr++) {
        const int r = r0 + rr;
        float2 v = *(const float2*)&s->Y[r][2 * l];
        *(float2*)&sol[((size_t)(row0 + r) * T_ + 0) * D_ + 2 * l] = v;
    }

    // FSAL: K[0] = f(Y), computed ONCE; maintained as invariant thereafter.
    // (k1 of any later step is f(Y) for the current Y: on accept it equals the
    //  k7=f(Y5) just computed; on reject Y is unchanged. Bit-exact vs reference.)
    feval(s, w, l, s->Y, s->K[0]);

    // dopri5 coefficients
    const float C2[1] = {0.2f};
    const float C3[2] = {3.f / 40.f, 9.f / 40.f};
    const float C4[3] = {44.f / 45.f, -56.f / 15.f, 32.f / 9.f};
    const float C5[4] = {19372.f / 6561.f, -25360.f / 2187.f, 64448.f / 6561.f, -212.f / 729.f};
    const float C6[5] = {9017.f / 3168.f, -355.f / 33.f, 46732.f / 5247.f, 49.f / 176.f,
                         -5103.f / 18656.f};
    const float CB[6] = {35.f / 384.f, 0.f, 500.f / 1113.f, 125.f / 192.f,
                         -2187.f / 6784.f, 11.f / 84.f};
    const float E1 = 71.f / 57600.f, E3 = -71.f / 16695.f, E4 = 71.f / 1920.f;
    const float E5 = -17253.f / 339200.f, E6 = 22.f / 525.f, E7 = -1.f / 40.f;

    float t  = times[0];
    float dt = times[1] - times[0];
    int sc = 0;  // executed-step counter (uniform across all CTAs)

    for (int ti = 0; ti < T_ - 1; ti++) {
        const float t_target = times[ti + 1];

        for (int iter = 0; iter < MAX_INNER; iter++) {
            const float remaining = t_target - t;
            if (remaining <= 0.0f) break;          // remaining iterations are exact no-ops
            const float dt_try = fminf(dt, remaining);

            // 6 stages (K[0] already valid via FSAL)
            build_stage<1>(s, w, l, dt_try, C2, s->Yt); feval(s, w, l, s->Yt, s->K[1]);
            build_stage<2>(s, w, l, dt_try, C3, s->Yt); feval(s, w, l, s->Yt, s->K[2]);
            build_stage<3>(s, w, l, dt_try, C4, s->Yt); feval(s, w, l, s->Yt, s->K[3]);
            build_stage<4>(s, w, l, dt_try, C5, s->Yt); feval(s, w, l, s->Yt, s->K[4]);
            build_stage<5>(s, w, l, dt_try, C6, s->Yt); feval(s, w, l, s->Yt, s->K[5]);
            build_stage<6>(s, w, l, dt_try, CB, s->Y5); feval(s, w, l, s->Y5, s->K[6]);

            // local error accumulation over this thread's lane-local elements
            float local = 0.f;
            #pragma unroll
            for (int rr = 0; rr < RPW; rr++) {
                const int r = r0 + rr;
                #pragma unroll
                for (int c = 0; c < 2; c++) {
                    const int d = 2 * l + c;
                    float e = E1 * s->K[0][r][d];
                    e = fmaf(E3, s->K[2][r][d], e);
                    e = fmaf(E4, s->K[3][r][d], e);
                    e = fmaf(E5, s->K[4][r][d], e);
                    e = fmaf(E6, s->K[5][r][d], e);
                    e = fmaf(E7, s->K[6][r][d], e);
                    e *= dt_try;
                    float scale = ATOL_ + RTOL_ * fmaxf(fabsf(s->Y[r][d]), fabsf(s->Y5[r][d]));
                    float q = e / scale;
                    local = fmaf(q, q, local);
                }
            }

            // deterministic CTA tree reduction (R6 verbatim)
            s->red[tid] = local;
            __syncthreads();
            #pragma unroll
            for (int off = TPB / 2; off > 0; off >>= 1) {
                if (tid < off) s->red[tid] += s->red[tid + off];
                __syncthreads();
            }
            if (tid == 0) g_part[sc & 1][blockIdx.x] = s->red[0];

            grid_barrier(tid);

            // parallel deterministic reduction of the 128 per-CTA partials (R6 verbatim)
            {
                const float* gp = g_part[sc & 1];
                s->red[tid] = gp[tid];          // TPB == NCTA == 128
                __syncthreads();
                #pragma unroll
                for (int off = TPB / 2; off > 0; off >>= 1) {
                    if (tid < off) s->red[tid] += s->red[tid + off];
                    __syncthreads();
                }
                if (tid == 0) s->s_ratio = sqrtf(s->red[0] / (float)NELEM);
                __syncthreads();
            }
            const float ratio = s->s_ratio;

            const bool accept = (ratio <= 1.0f);
            if (accept) {
                t = t + dt_try;
                #pragma unroll
                for (int rr = 0; rr < RPW; rr++) {
                    const int r = r0 + rr;
                    *(float2*)&s->Y[r][2 * l] = *(const float2*)&s->Y5[r][2 * l];
                    // FSAL: next k1 = f(Y5) = k7, already in K[6]
                    *(float2*)&s->K[0][r][2 * l] = *(const float2*)&s->K[6][r][2 * l];
                }
            }
            float factor = 0.9f * powf(fmaxf(ratio, 1e-10f), -0.2f);
            factor = fminf(fmaxf(factor, 0.2f), 10.0f);
            dt = dt * factor;
            sc++;
            __syncwarp();
        }

        t = t_target;  // snap to target (matches reference)

        // write accepted state for this interval (coalesced)
        __syncwarp();
        #pragma unroll
        for (int rr = 0; rr < RPW; rr++) {
            const int r = r0 + rr;
            float2 v = *(const float2*)&s->Y[r][2 * l];
            *(float2*)&sol[((size_t)(row0 + r) * T_ + (ti + 1)) * D_ + 2 * l] = v;
        }
    }
}

// ---------------- decode kernel: pred = sol_z @ Wo + bo (R8 proven, pred-only) ----
#define DEC_ROWS 32
__global__ void __launch_bounds__(256)
decode_kernel(const float* __restrict__ gWo, const float* __restrict__ gbo,
              const float* __restrict__ sol_src, float* __restrict__ pred_out) {
    __shared__ float sWo[D_][O_];        // 32 KB
    __shared__ float sbo[O_];
    __shared__ float sx[DEC_ROWS][D_];   // 8 KB

    const int tid = threadIdx.x;
    for (int i = tid; i < D_ * O_; i += 256) ((float*)sWo)[i] = gWo[i];
    for (int i = tid; i < O_; i += 256) sbo[i] = gbo[i];

    const size_t row0 = (size_t)blockIdx.x * DEC_ROWS;
    for (int i = tid; i < DEC_ROWS * D_; i += 256)
        ((float*)sx)[i] = sol_src[row0 * D_ + i];
    __syncthreads();

    const int w = tid >> 5;
    const int l = tid & 31;
    const int rb = w * 4;                // 8 warps x 4 rows = 32 rows

    u64 a0[4], a1[4];
    {
        const u64* bop = (const u64*)sbo;
        u64 i0 = bop[2 * l], i1 = bop[2 * l + 1];
        #pragma unroll
        for (int rr = 0; rr < 4; rr++) { a0[rr] = i0; a1[rr] = i1; }
    }
    #pragma unroll 4
    for (int d0 = 0; d0 < D_; d0 += 4) {
        ulonglong2 wq[4];
        #pragma unroll
        for (int dd = 0; dd < 4; dd++)
            wq[dd] = *(const ulonglong2*)&sWo[d0 + dd][4 * l];
        float4 xv[4];
        #pragma unroll
        for (int rr = 0; rr < 4; rr++)
            xv[rr] = *(const float4*)&sx[rb + rr][d0];
        #pragma unroll
        for (int dd = 0; dd < 4; dd++) {
            #pragma unroll
            for (int rr = 0; rr < 4; rr++) {
                float x = (dd == 0) ? xv[rr].x : (dd == 1) ? xv[rr].y
                        : (dd == 2) ? xv[rr].z : xv[rr].w;
                u64 xd = dup2(x);
                a0[rr] = ffma2(xd, wq[dd].x, a0[rr]);
                a1[rr] = ffma2(xd, wq[dd].y, a1[rr]);
            }
        }
    }
    #pragma unroll
    for (int rr = 0; rr < 4; rr++) {
        const size_t r = row0 + rb + rr;
        float2 lo = u2f2(a0[rr]), hi = u2f2(a1[rr]);
        *(float4*)&pred_out[r * O_ + 4 * l] = make_float4(lo.x, lo.y, hi.x, hi.y);
    }
}

// ---------------- launch ----------------
extern "C" void kernel_launch(void* const* d_in, const int* in_sizes, int n_in,
                              void* d_out, int out_size) {
    const float* first_point = (const float*)d_in[0];
    const float* times       = (const float*)d_in[1];
    const float* W1          = (const float*)d_in[2];
    const float* b1          = (const float*)d_in[3];
    const float* W2          = (const float*)d_in[4];
    const float* b2          = (const float*)d_in[5];
    const float* Wo          = (const float*)d_in[6];
    const float* bo          = (const float*)d_in[7];

    float* out = (float*)d_out;
    const long long NS = (long long)NROW * T_ * D_;   // 12,582,912 (sol_z)
    const long long NP = (long long)NROW * T_ * O_;   // 25,165,824 (pred_x)

    float* sol_dst;
    float* pred_out;
    if ((long long)out_size == NS + NP)      { sol_dst = out;  pred_out = out + NS; }
    else if ((long long)out_size == NP) {
        float* gsol_ptr = nullptr;
        cudaGetSymbolAddress((void**)&gsol_ptr, g_sol);
        sol_dst = gsol_ptr; pred_out = out;
    }
    else if ((long long)out_size == NS)      { sol_dst = out;  pred_out = nullptr; }
    else                                     { sol_dst = out;  pred_out = out + NS; }

    cudaFuncSetAttribute(ode_kernel, cudaFuncAttributeMaxDynamicSharedMemorySize, SMEM_BYTES);

    ode_kernel<<<NCTA, TPB, SMEM_BYTES>>>(first_point, times, W1, b1, W2, b2, sol_dst);

    if (pred_out)
        decode_kernel<<<(NROW * T_) / DEC_ROWS, 256>>>(Wo, bo, sol_dst, pred_out);
}

// round 16
// speedup vs baseline: 1.6268x; 1.6268x over previous
#include <cuda_runtime.h>
#include <cuda_bf16.h>
#include <cstdint>
#include <math.h>

// ---------------- problem constants ----------------
#define S_    3
#define B_    1024
#define D_    64
#define H_    128
#define O_    128
#define T_    64
#define NROW  3072                    // S_*B_
#define NELEM (NROW * D_)             // 196608
#define RTOL_ 1e-4f
#define ATOL_ 1e-5f
#define MAX_INNER 12

// ---------------- kernel config (round-6 proven) ----------------
#define NCTA 128
#define TPB  128                      // 4 warps
#define NW   4
#define RPW  6                        // rows per warp
#define RPC  24                       // rows per CTA

typedef unsigned long long u64;

// ---------------- packed f32x2 helpers ----------------
__device__ __forceinline__ u64 ffma2(u64 a, u64 b, u64 c) {
    u64 d; asm("fma.rn.f32x2 %0, %1, %2, %3;" : "=l"(d) : "l"(a), "l"(b), "l"(c)); return d;
}
__device__ __forceinline__ u64 dup2(float v) {
    u64 r; asm("mov.b64 %0, {%1, %1};" : "=l"(r) : "f"(v)); return r;
}
__device__ __forceinline__ float2 u2f2(u64 v) {
    float2 f; asm("mov.b64 {%0, %1}, %2;" : "=f"(f.x), "=f"(f.y) : "l"(v)); return f;
}

// fast tanh via MUFU.EX2 + MUFU.RCP: t = (e^{2x}-1)/(e^{2x}+1).
__device__ __forceinline__ float fast_tanh(float x) {
    float xc = fminf(fmaxf(x, -15.f), 15.f);   // overflow guard
    float a = __expf(2.f * xc);
    return __fdividef(a - 1.f, a + 1.f);
}

// ---------------- shared memory layout (round-6 verbatim) ----------------
struct Smem {
    float W1[D_][H_];       // 32 KB
    float W2[H_][D_];       // 32 KB
    float b1[H_];
    float b2[D_];
    float Y [RPC][D_];
    float Y5[RPC][D_];
    float Yt[RPC][D_];
    float Hh[RPC][H_];      // 12 KB
    float K [7][RPC][D_];   // 42 KB
    float red[TPB];
    float s_ratio;
};
#define SMEM_BYTES ((int)sizeof(Smem))

// ---------------- device globals (scratch; no allocations allowed) ----------------
__device__ unsigned g_bar = 0;                         // monotone barrier counter
__device__ float    g_part[2][NCTA];                   // per-CTA partial err sums
__device__ float    g_sol[(size_t)NROW * T_ * D_];     // fallback sol_z scratch

// ---------------- grid-wide barrier (all NCTA CTAs co-resident) ----------------
__device__ __forceinline__ void grid_barrier(int tid) {
    __syncthreads();
    if (tid == 0) {
        __threadfence();
        unsigned arrival = atomicAdd(&g_bar, 1u);
        unsigned target = arrival - (arrival % NCTA) + NCTA;
        while ((int)(*(volatile unsigned*)&g_bar - target) < 0) {
            __nanosleep(64);
        }
        __threadfence();
    }
    __syncthreads();
}

// ---------------- f(Yin) -> Kout : two smem GEMMs, warp-local rows (R14 verbatim) -
// lane l owns cols 4l..4l+3 (stage A) and 2l..2l+1 (stage B).
__device__ __forceinline__ void feval(Smem* s, int w, int l,
                                      const float (*Yin)[D_], float (*Kout)[D_]) {
    __syncwarp();
    const int r0 = w * RPW;

    // ---- stage A: Hh = tanh(Yin @ W1 + b1) ----
    u64 acc0[RPW], acc1[RPW];
    {
        const u64* b1p = (const u64*)s->b1;
        u64 i0 = b1p[2 * l], i1 = b1p[2 * l + 1];
        #pragma unroll
        for (int rr = 0; rr < RPW; rr++) { acc0[rr] = i0; acc1[rr] = i1; }
    }
    #pragma unroll 4
    for (int d0 = 0; d0 < D_; d0 += 4) {
        ulonglong2 wq[4];
        #pragma unroll
        for (int dd = 0; dd < 4; dd++)
            wq[dd] = *(const ulonglong2*)&s->W1[d0 + dd][4 * l];
        float4 yv[RPW];
        #pragma unroll
        for (int rr = 0; rr < RPW; rr++)
            yv[rr] = *(const float4*)&Yin[r0 + rr][d0];        // warp-broadcast, 4 y's
        #pragma unroll
        for (int dd = 0; dd < 4; dd++) {
            #pragma unroll
            for (int rr = 0; rr < RPW; rr++) {
                float y = (dd == 0) ? yv[rr].x : (dd == 1) ? yv[rr].y
                        : (dd == 2) ? yv[rr].z : yv[rr].w;
                u64 yd = dup2(y);
                acc0[rr] = ffma2(yd, wq[dd].x, acc0[rr]);
                acc1[rr] = ffma2(yd, wq[dd].y, acc1[rr]);
            }
        }
    }
    #pragma unroll
    for (int rr = 0; rr < RPW; rr++) {
        float2 p0 = u2f2(acc0[rr]), p1 = u2f2(acc1[rr]);
        float4 hv = make_float4(fast_tanh(p0.x), fast_tanh(p0.y),
                                fast_tanh(p1.x), fast_tanh(p1.y));
        *(float4*)&s->Hh[r0 + rr][4 * l] = hv;
    }
    __syncwarp();

    // ---- stage B: Kout = Hh @ W2 + b2 ----
    u64 a2[RPW];
    {
        u64 ib = ((const u64*)s->b2)[l];
        #pragma unroll
        for (int rr = 0; rr < RPW; rr++) a2[rr] = ib;
    }
    #pragma unroll 4
    for (int j0 = 0; j0 < H_; j0 += 4) {
        u64 w2q[4];
        #pragma unroll
        for (int dd = 0; dd < 4; dd++)
            w2q[dd] = *(const u64*)&s->W2[j0 + dd][2 * l];
        float4 hv[RPW];
        #pragma unroll
        for (int rr = 0; rr < RPW; rr++)
            hv[rr] = *(const float4*)&s->Hh[r0 + rr][j0];      // warp-broadcast, 4 h's
        #pragma unroll
        for (int dd = 0; dd < 4; dd++) {
            #pragma unroll
            for (int rr = 0; rr < RPW; rr++) {
                float h = (dd == 0) ? hv[rr].x : (dd == 1) ? hv[rr].y
                        : (dd == 2) ? hv[rr].z : hv[rr].w;
                a2[rr] = ffma2(dup2(h), w2q[dd], a2[rr]);
            }
        }
    }
    #pragma unroll
    for (int rr = 0; rr < RPW; rr++)
        *(u64*)&Kout[r0 + rr][2 * l] = a2[rr];
    __syncwarp();
}

// ---- Out = Y + dt * sum(cf[kk]*K[kk]), lane-local columns (R6 verbatim) ----
template <int NK>
__device__ __forceinline__ void build_stage(Smem* s, int w, int l, float dtv,
                                            const float* cf, float (*Out)[D_]) {
    const int r0 = w * RPW;
    #pragma unroll
    for (int rr = 0; rr < RPW; rr++) {
        const int r = r0 + rr;
        #pragma unroll
        for (int c = 0; c < 2; c++) {
            const int d = 2 * l + c;
            float acc = 0.f;
            #pragma unroll
            for (int kk = 0; kk < NK; kk++)
                acc = fmaf(cf[kk], s->K[kk][r][d], acc);
            Out[r][d] = fmaf(dtv, acc, s->Y[r][d]);
        }
    }
}

// ---------------- persistent ODE solver kernel ----------------
__global__ void __launch_bounds__(TPB, 1)
ode_kernel(const float* __restrict__ first_point,
           const float* __restrict__ times,
           const float* __restrict__ gW1, const float* __restrict__ gb1,
           const float* __restrict__ gW2, const float* __restrict__ gb2,
           float* __restrict__ sol) {
    extern __shared__ char smem_raw[];
    Smem* s = (Smem*)smem_raw;

    const int tid = threadIdx.x;
    const int w = tid >> 5;
    const int l = tid & 31;
    const int row0 = blockIdx.x * RPC;
    const int r0 = w * RPW;

    // load weights + initial state
    for (int i = tid; i < D_ * H_; i += TPB) ((float*)s->W1)[i] = gW1[i];
    for (int i = tid; i < H_ * D_; i += TPB) ((float*)s->W2)[i] = gW2[i];
    for (int i = tid; i < H_; i += TPB) s->b1[i] = gb1[i];
    for (int i = tid; i < D_; i += TPB) s->b2[i] = gb2[i];
    for (int i = tid; i < RPC * D_; i += TPB)
        ((float*)s->Y)[i] = first_point[(size_t)row0 * D_ + i];
    __syncthreads();

    // sol at t index 0 (coalesced float2)
    #pragma unroll
    for (int rr = 0; rr < RPW; rr++) {
        const int r = r0 + rr;
        float2 v = *(const float2*)&s->Y[r][2 * l];
        *(float2*)&sol[((size_t)(row0 + r) * T_ + 0) * D_ + 2 * l] = v;
    }

    // FSAL: K[0] = f(Y), computed ONCE; maintained as invariant thereafter.
    // (k1 of any later step is f(Y) for the current Y: on accept it equals the
    //  k7=f(Y5) just computed; on reject Y is unchanged. Bit-exact vs reference.)
    feval(s, w, l, s->Y, s->K[0]);

    // dopri5 coefficients
    const float C2[1] = {0.2f};
    const float C3[2] = {3.f / 40.f, 9.f / 40.f};
    const float C4[3] = {44.f / 45.f, -56.f / 15.f, 32.f / 9.f};
    const float C5[4] = {19372.f / 6561.f, -25360.f / 2187.f, 64448.f / 6561.f, -212.f / 729.f};
    const float C6[5] = {9017.f / 3168.f, -355.f / 33.f, 46732.f / 5247.f, 49.f / 176.f,
                         -5103.f / 18656.f};
    const float CB[6] = {35.f / 384.f, 0.f, 500.f / 1113.f, 125.f / 192.f,
                         -2187.f / 6784.f, 11.f / 84.f};
    const float E1 = 71.f / 57600.f, E3 = -71.f / 16695.f, E4 = 71.f / 1920.f;
    const float E5 = -17253.f / 339200.f, E6 = 22.f / 525.f, E7 = -1.f / 40.f;

    float t  = times[0];
    float dt = times[1] - times[0];
    int sc = 0;  // executed-step counter (uniform across all CTAs)

    for (int ti = 0; ti < T_ - 1; ti++) {
        const float t_target = times[ti + 1];

        for (int iter = 0; iter < MAX_INNER; iter++) {
            const float remaining = t_target - t;
            if (remaining <= 0.0f) break;          // remaining iterations are exact no-ops
            const float dt_try = fminf(dt, remaining);

            // 6 stages (K[0] already valid via FSAL)
            build_stage<1>(s, w, l, dt_try, C2, s->Yt); feval(s, w, l, s->Yt, s->K[1]);
            build_stage<2>(s, w, l, dt_try, C3, s->Yt); feval(s, w, l, s->Yt, s->K[2]);
            build_stage<3>(s, w, l, dt_try, C4, s->Yt); feval(s, w, l, s->Yt, s->K[3]);
            build_stage<4>(s, w, l, dt_try, C5, s->Yt); feval(s, w, l, s->Yt, s->K[4]);
            build_stage<5>(s, w, l, dt_try, C6, s->Yt); feval(s, w, l, s->Yt, s->K[5]);
            build_stage<6>(s, w, l, dt_try, CB, s->Y5); feval(s, w, l, s->Y5, s->K[6]);

            // local error accumulation over this thread's lane-local elements
            float local = 0.f;
            #pragma unroll
            for (int rr = 0; rr < RPW; rr++) {
                const int r = r0 + rr;
                #pragma unroll
                for (int c = 0; c < 2; c++) {
                    const int d = 2 * l + c;
                    float e = E1 * s->K[0][r][d];
                    e = fmaf(E3, s->K[2][r][d], e);
                    e = fmaf(E4, s->K[3][r][d], e);
                    e = fmaf(E5, s->K[4][r][d], e);
                    e = fmaf(E6, s->K[5][r][d], e);
                    e = fmaf(E7, s->K[6][r][d], e);
                    e *= dt_try;
                    float scale = ATOL_ + RTOL_ * fmaxf(fabsf(s->Y[r][d]), fabsf(s->Y5[r][d]));
                    float q = e / scale;
                    local = fmaf(q, q, local);
                }
            }

            // deterministic CTA tree reduction (R6 verbatim)
            s->red[tid] = local;
            __syncthreads();
            #pragma unroll
            for (int off = TPB / 2; off > 0; off >>= 1) {
                if (tid < off) s->red[tid] += s->red[tid + off];
                __syncthreads();
            }
            if (tid == 0) g_part[sc & 1][blockIdx.x] = s->red[0];

            grid_barrier(tid);

            // parallel deterministic reduction of the 128 per-CTA partials (R6 verbatim)
            {
                const float* gp = g_part[sc & 1];
                s->red[tid] = gp[tid];          // TPB == NCTA == 128
                __syncthreads();
                #pragma unroll
                for (int off = TPB / 2; off > 0; off >>= 1) {
                    if (tid < off) s->red[tid] += s->red[tid + off];
                    __syncthreads();
                }
                if (tid == 0) s->s_ratio = sqrtf(s->red[0] / (float)NELEM);
                __syncthreads();
            }
            const float ratio = s->s_ratio;

            const bool accept = (ratio <= 1.0f);
            if (accept) {
                t = t + dt_try;
                #pragma unroll
                for (int rr = 0; rr < RPW; rr++) {
                    const int r = r0 + rr;
                    *(float2*)&s->Y[r][2 * l] = *(const float2*)&s->Y5[r][2 * l];
                    // FSAL: next k1 = f(Y5) = k7, already in K[6]
                    *(float2*)&s->K[0][r][2 * l] = *(const float2*)&s->K[6][r][2 * l];
                }
            }
            float factor = 0.9f * powf(fmaxf(ratio, 1e-10f), -0.2f);
            factor = fminf(fmaxf(factor, 0.2f), 10.0f);
            dt = dt * factor;
            sc++;
            __syncwarp();
        }

        t = t_target;  // snap to target (matches reference)

        // write accepted state for this interval (coalesced)
        __syncwarp();
        #pragma unroll
        for (int rr = 0; rr < RPW; rr++) {
            const int r = r0 + rr;
            float2 v = *(const float2*)&s->Y[r][2 * l];
            *(float2*)&sol[((size_t)(row0 + r) * T_ + (ti + 1)) * D_ + 2 * l] = v;
        }
    }
}

// ---------------- decode kernel: pred = sol_z @ Wo + bo (R8 proven, pred-only) ----
#define DEC_ROWS 32
__global__ void __launch_bounds__(256)
decode_kernel(const float* __restrict__ gWo, const float* __restrict__ gbo,
              const float* __restrict__ sol_src, float* __restrict__ pred_out) {
    __shared__ float sWo[D_][O_];        // 32 KB
    __shared__ float sbo[O_];
    __shared__ float sx[DEC_ROWS][D_];   // 8 KB

    const int tid = threadIdx.x;
    for (int i = tid; i < D_ * O_; i += 256) ((float*)sWo)[i] = gWo[i];
    for (int i = tid; i < O_; i += 256) sbo[i] = gbo[i];

    const size_t row0 = (size_t)blockIdx.x * DEC_ROWS;
    for (int i = tid; i < DEC_ROWS * D_; i += 256)
        ((float*)sx)[i] = sol_src[row0 * D_ + i];
    __syncthreads();

    const int w = tid >> 5;
    const int l = tid & 31;
    const int rb = w * 4;                // 8 warps x 4 rows = 32 rows

    u64 a0[4], a1[4];
    {
        const u64* bop = (const u64*)sbo;
        u64 i0 = bop[2 * l], i1 = bop[2 * l + 1];
        #pragma unroll
        for (int rr = 0; rr < 4; rr++) { a0[rr] = i0; a1[rr] = i1; }
    }
    #pragma unroll 4
    for (int d0 = 0; d0 < D_; d0 += 4) {
        ulonglong2 wq[4];
        #pragma unroll
        for (int dd = 0; dd < 4; dd++)
            wq[dd] = *(const ulonglong2*)&sWo[d0 + dd][4 * l];
        float4 xv[4];
        #pragma unroll
        for (int rr = 0; rr < 4; rr++)
            xv[rr] = *(const float4*)&sx[rb + rr][d0];
        #pragma unroll
        for (int dd = 0; dd < 4; dd++) {
            #pragma unroll
            for (int rr = 0; rr < 4; rr++) {
                float x = (dd == 0) ? xv[rr].x : (dd == 1) ? xv[rr].y
                        : (dd == 2) ? xv[rr].z : xv[rr].w;
                u64 xd = dup2(x);
                a0[rr] = ffma2(xd, wq[dd].x, a0[rr]);
                a1[rr] = ffma2(xd, wq[dd].y, a1[rr]);
            }
        }
    }
    #pragma unroll
    for (int rr = 0; rr < 4; rr++) {
        const size_t r = row0 + rb + rr;
        float2 lo = u2f2(a0[rr]), hi = u2f2(a1[rr]);
        *(float4*)&pred_out[r * O_ + 4 * l] = make_float4(lo.x, lo.y, hi.x, hi.y);
    }
}

// ---------------- launch ----------------
extern "C" void kernel_launch(void* const* d_in, const int* in_sizes, int n_in,
                              void* d_out, int out_size) {
    const float* first_point = (const float*)d_in[0];
    const float* times       = (const float*)d_in[1];
    const float* W1          = (const float*)d_in[2];
    const float* b1          = (const float*)d_in[3];
    const float* W2          = (const float*)d_in[4];
    const float* b2          = (const float*)d_in[5];
    const float* Wo          = (const float*)d_in[6];
    const float* bo          = (const float*)d_in[7];

    float* out = (float*)d_out;
    const long long NS = (long long)NROW * T_ * D_;   // 12,582,912 (sol_z)
    const long long NP = (long long)NROW * T_ * O_;   // 25,165,824 (pred_x)

    float* sol_dst;
    float* pred_out;
    if ((long long)out_size == NS + NP)      { sol_dst = out;  pred_out = out + NS; }
    else if ((long long)out_size == NP) {
        float* gsol_ptr = nullptr;
        cudaGetSymbolAddress((void**)&gsol_ptr, g_sol);
        sol_dst = gsol_ptr; pred_out = out;
    }
    else if ((long long)out_size == NS)      { sol_dst = out;  pred_out = nullptr; }
    else                                     { sol_dst = out;  pred_out = out + NS; }

    cudaFuncSetAttribute(ode_kernel, cudaFuncAttributeMaxDynamicSharedMemorySize, SMEM_BYTES);

    ode_kernel<<<NCTA, TPB, SMEM_BYTES>>>(first_point, times, W1, b1, W2, b2, sol_dst);

    if (pred_out)
        decode_kernel<<<(NROW * T_) / DEC_ROWS, 256>>>(Wo, bo, sol_dst, pred_out);
}

// round 17
// speedup vs baseline: 1.6400x; 1.0081x over previous
#include <cuda_runtime.h>
#include <cuda_bf16.h>
#include <cstdint>
#include <math.h>

// ---------------- problem constants ----------------
#define S_    3
#define B_    1024
#define D_    64
#define H_    128
#define O_    128
#define T_    64
#define NROW  3072                    // S_*B_
#define NELEM (NROW * D_)             // 196608
#define RTOL_ 1e-4f
#define ATOL_ 1e-5f
#define MAX_INNER 12

// ---------------- kernel config (round-6 proven) ----------------
#define NCTA 128
#define TPB  128                      // 4 warps
#define NW   4
#define RPW  6                        // rows per warp
#define RPC  24                       // rows per CTA

typedef unsigned long long u64;

// ---------------- packed f32x2 helpers ----------------
__device__ __forceinline__ u64 ffma2(u64 a, u64 b, u64 c) {
    u64 d; asm("fma.rn.f32x2 %0, %1, %2, %3;" : "=l"(d) : "l"(a), "l"(b), "l"(c)); return d;
}
__device__ __forceinline__ u64 dup2(float v) {
    u64 r; asm("mov.b64 %0, {%1, %1};" : "=l"(r) : "f"(v)); return r;
}
__device__ __forceinline__ float2 u2f2(u64 v) {
    float2 f; asm("mov.b64 {%0, %1}, %2;" : "=f"(f.x), "=f"(f.y) : "l"(v)); return f;
}

// fast tanh via MUFU.EX2 + MUFU.RCP: t = (e^{2x}-1)/(e^{2x}+1).
__device__ __forceinline__ float fast_tanh(float x) {
    float xc = fminf(fmaxf(x, -15.f), 15.f);   // overflow guard
    float a = __expf(2.f * xc);
    return __fdividef(a - 1.f, a + 1.f);
}

// ---------------- shared memory layout (round-6 verbatim) ----------------
struct Smem {
    float W1[D_][H_];       // 32 KB
    float W2[H_][D_];       // 32 KB
    float b1[H_];
    float b2[D_];
    float Y [RPC][D_];
    float Y5[RPC][D_];
    float Yt[RPC][D_];
    float Hh[RPC][H_];      // 12 KB
    float K [7][RPC][D_];   // 42 KB
    float red[NW];
    float s_ratio;
};
#define SMEM_BYTES ((int)sizeof(Smem))

// ---------------- device globals (scratch; no allocations allowed) ----------------
__device__ unsigned g_bar = 0;                         // monotone barrier counter
__device__ float    g_part[2][NCTA];                   // per-CTA partial err sums
__device__ float    g_sol[(size_t)NROW * T_ * D_];     // fallback sol_z scratch

// ---------------- grid-wide barrier (all NCTA CTAs co-resident) ----------------
__device__ __forceinline__ void grid_barrier(int tid) {
    __syncthreads();
    if (tid == 0) {
        __threadfence();
        unsigned arrival = atomicAdd(&g_bar, 1u);
        unsigned target = arrival - (arrival % NCTA) + NCTA;
        while ((int)(*(volatile unsigned*)&g_bar - target) < 0) {
            __nanosleep(64);
        }
        __threadfence();
    }
    __syncthreads();
}

// ---------------- f(Yin) -> Kout : two smem GEMMs, warp-local rows (R14 verbatim) -
// lane l owns cols 4l..4l+3 (stage A) and 2l..2l+1 (stage B).
__device__ __forceinline__ void feval(Smem* s, int w, int l,
                                      const float (*Yin)[D_], float (*Kout)[D_]) {
    __syncwarp();
    const int r0 = w * RPW;

    // ---- stage A: Hh = tanh(Yin @ W1 + b1) ----
    u64 acc0[RPW], acc1[RPW];
    {
        const u64* b1p = (const u64*)s->b1;
        u64 i0 = b1p[2 * l], i1 = b1p[2 * l + 1];
        #pragma unroll
        for (int rr = 0; rr < RPW; rr++) { acc0[rr] = i0; acc1[rr] = i1; }
    }
    #pragma unroll 4
    for (int d0 = 0; d0 < D_; d0 += 4) {
        ulonglong2 wq[4];
        #pragma unroll
        for (int dd = 0; dd < 4; dd++)
            wq[dd] = *(const ulonglong2*)&s->W1[d0 + dd][4 * l];
        float4 yv[RPW];
        #pragma unroll
        for (int rr = 0; rr < RPW; rr++)
            yv[rr] = *(const float4*)&Yin[r0 + rr][d0];        // warp-broadcast, 4 y's
        #pragma unroll
        for (int dd = 0; dd < 4; dd++) {
            #pragma unroll
            for (int rr = 0; rr < RPW; rr++) {
                float y = (dd == 0) ? yv[rr].x : (dd == 1) ? yv[rr].y
                        : (dd == 2) ? yv[rr].z : yv[rr].w;
                u64 yd = dup2(y);
                acc0[rr] = ffma2(yd, wq[dd].x, acc0[rr]);
                acc1[rr] = ffma2(yd, wq[dd].y, acc1[rr]);
            }
        }
    }
    #pragma unroll
    for (int rr = 0; rr < RPW; rr++) {
        float2 p0 = u2f2(acc0[rr]), p1 = u2f2(acc1[rr]);
        float4 hv = make_float4(fast_tanh(p0.x), fast_tanh(p0.y),
                                fast_tanh(p1.x), fast_tanh(p1.y));
        *(float4*)&s->Hh[r0 + rr][4 * l] = hv;
    }
    __syncwarp();

    // ---- stage B: Kout = Hh @ W2 + b2 ----
    u64 a2[RPW];
    {
        u64 ib = ((const u64*)s->b2)[l];
        #pragma unroll
        for (int rr = 0; rr < RPW; rr++) a2[rr] = ib;
    }
    #pragma unroll 4
    for (int j0 = 0; j0 < H_; j0 += 4) {
        u64 w2q[4];
        #pragma unroll
        for (int dd = 0; dd < 4; dd++)
            w2q[dd] = *(const u64*)&s->W2[j0 + dd][2 * l];
        float4 hv[RPW];
        #pragma unroll
        for (int rr = 0; rr < RPW; rr++)
            hv[rr] = *(const float4*)&s->Hh[r0 + rr][j0];      // warp-broadcast, 4 h's
        #pragma unroll
        for (int dd = 0; dd < 4; dd++) {
            #pragma unroll
            for (int rr = 0; rr < RPW; rr++) {
                float h = (dd == 0) ? hv[rr].x : (dd == 1) ? hv[rr].y
                        : (dd == 2) ? hv[rr].z : hv[rr].w;
                a2[rr] = ffma2(dup2(h), w2q[dd], a2[rr]);
            }
        }
    }
    #pragma unroll
    for (int rr = 0; rr < RPW; rr++)
        *(u64*)&Kout[r0 + rr][2 * l] = a2[rr];
    __syncwarp();
}

// ---- Out = Y + dt * sum(cf[kk]*K[kk]), lane-local columns (R6 verbatim) ----
template <int NK>
__device__ __forceinline__ void build_stage(Smem* s, int w, int l, float dtv,
                                            const float* cf, float (*Out)[D_]) {
    const int r0 = w * RPW;
    #pragma unroll
    for (int rr = 0; rr < RPW; rr++) {
        const int r = r0 + rr;
        #pragma unroll
        for (int c = 0; c < 2; c++) {
            const int d = 2 * l + c;
            float acc = 0.f;
            #pragma unroll
            for (int kk = 0; kk < NK; kk++)
                acc = fmaf(cf[kk], s->K[kk][r][d], acc);
            Out[r][d] = fmaf(dtv, acc, s->Y[r][d]);
        }
    }
}

// ---------------- persistent ODE solver kernel ----------------
__global__ void __launch_bounds__(TPB, 1)
ode_kernel(const float* __restrict__ first_point,
           const float* __restrict__ times,
           const float* __restrict__ gW1, const float* __restrict__ gb1,
           const float* __restrict__ gW2, const float* __restrict__ gb2,
           float* __restrict__ sol) {
    extern __shared__ char smem_raw[];
    Smem* s = (Smem*)smem_raw;

    const int tid = threadIdx.x;
    const int w = tid >> 5;
    const int l = tid & 31;
    const int row0 = blockIdx.x * RPC;
    const int r0 = w * RPW;

    // load weights + initial state
    for (int i = tid; i < D_ * H_; i += TPB) ((float*)s->W1)[i] = gW1[i];
    for (int i = tid; i < H_ * D_; i += TPB) ((float*)s->W2)[i] = gW2[i];
    for (int i = tid; i < H_; i += TPB) s->b1[i] = gb1[i];
    for (int i = tid; i < D_; i += TPB) s->b2[i] = gb2[i];
    for (int i = tid; i < RPC * D_; i += TPB)
        ((float*)s->Y)[i] = first_point[(size_t)row0 * D_ + i];
    __syncthreads();

    // sol at t index 0 (coalesced float2)
    #pragma unroll
    for (int rr = 0; rr < RPW; rr++) {
        const int r = r0 + rr;
        float2 v = *(const float2*)&s->Y[r][2 * l];
        *(float2*)&sol[((size_t)(row0 + r) * T_ + 0) * D_ + 2 * l] = v;
    }

    // FSAL: K[0] = f(Y), computed ONCE; maintained as invariant thereafter.
    feval(s, w, l, s->Y, s->K[0]);

    // dopri5 coefficients
    const float C2[1] = {0.2f};
    const float C3[2] = {3.f / 40.f, 9.f / 40.f};
    const float C4[3] = {44.f / 45.f, -56.f / 15.f, 32.f / 9.f};
    const float C5[4] = {19372.f / 6561.f, -25360.f / 2187.f, 64448.f / 6561.f, -212.f / 729.f};
    const float C6[5] = {9017.f / 3168.f, -355.f / 33.f, 46732.f / 5247.f, 49.f / 176.f,
                         -5103.f / 18656.f};
    const float CB[6] = {35.f / 384.f, 0.f, 500.f / 1113.f, 125.f / 192.f,
                         -2187.f / 6784.f, 11.f / 84.f};
    const float E1 = 71.f / 57600.f, E3 = -71.f / 16695.f, E4 = 71.f / 1920.f;
    const float E5 = -17253.f / 339200.f, E6 = 22.f / 525.f, E7 = -1.f / 40.f;

    float t  = times[0];
    float dt = times[1] - times[0];
    int sc = 0;  // executed-step counter (uniform across all CTAs)

    for (int ti = 0; ti < T_ - 1; ti++) {
        const float t_target = times[ti + 1];

        for (int iter = 0; iter < MAX_INNER; iter++) {
            const float remaining = t_target - t;
            if (remaining <= 0.0f) break;          // remaining iterations are exact no-ops
            const float dt_try = fminf(dt, remaining);

            // 6 stages (K[0] already valid via FSAL)
            build_stage<1>(s, w, l, dt_try, C2, s->Yt); feval(s, w, l, s->Yt, s->K[1]);
            build_stage<2>(s, w, l, dt_try, C3, s->Yt); feval(s, w, l, s->Yt, s->K[2]);
            build_stage<3>(s, w, l, dt_try, C4, s->Yt); feval(s, w, l, s->Yt, s->K[3]);
            build_stage<4>(s, w, l, dt_try, C5, s->Yt); feval(s, w, l, s->Yt, s->K[4]);
            build_stage<5>(s, w, l, dt_try, C6, s->Yt); feval(s, w, l, s->Yt, s->K[5]);
            build_stage<6>(s, w, l, dt_try, CB, s->Y5); feval(s, w, l, s->Y5, s->K[6]);

            // local error accumulation over this thread's lane-local elements
            float local = 0.f;
            #pragma unroll
            for (int rr = 0; rr < RPW; rr++) {
                const int r = r0 + rr;
                #pragma unroll
                for (int c = 0; c < 2; c++) {
                    const int d = 2 * l + c;
                    float e = E1 * s->K[0][r][d];
                    e = fmaf(E3, s->K[2][r][d], e);
                    e = fmaf(E4, s->K[3][r][d], e);
                    e = fmaf(E5, s->K[4][r][d], e);
                    e = fmaf(E6, s->K[5][r][d], e);
                    e = fmaf(E7, s->K[6][r][d], e);
                    e *= dt_try;
                    float scale = ATOL_ + RTOL_ * fmaxf(fabsf(s->Y[r][d]), fabsf(s->Y5[r][d]));
                    float q = e / scale;
                    local = fmaf(q, q, local);
                }
            }

            // CTA reduction: warp shfl tree + warp-0 pass over the 4 warp sums
            #pragma unroll
            for (int off = 16; off > 0; off >>= 1)
                local += __shfl_xor_sync(0xffffffffu, local, off);
            if (l == 0) s->red[w] = local;
            __syncthreads();
            if (w == 0) {
                float v = (l < NW) ? s->red[l] : 0.f;
                v += __shfl_xor_sync(0xffffffffu, v, 2);
                v += __shfl_xor_sync(0xffffffffu, v, 1);
                if (l == 0) g_part[sc & 1][blockIdx.x] = v;
            }

            grid_barrier(tid);

            // global reduction of the 128 per-CTA partials (warp 0, L2 loads)
            if (w == 0) {
                const float* gp = g_part[sc & 1];
                float v = __ldcg(&gp[l]) + __ldcg(&gp[l + 32])
                        + __ldcg(&gp[l + 64]) + __ldcg(&gp[l + 96]);
                #pragma unroll
                for (int off = 16; off > 0; off >>= 1)
                    v += __shfl_xor_sync(0xffffffffu, v, off);
                if (l == 0) s->s_ratio = sqrtf(v / (float)NELEM);
            }
            __syncthreads();
            const float ratio = s->s_ratio;

            const bool accept = (ratio <= 1.0f);
            if (accept) {
                t = t + dt_try;
                #pragma unroll
                for (int rr = 0; rr < RPW; rr++) {
                    const int r = r0 + rr;
                    *(float2*)&s->Y[r][2 * l] = *(const float2*)&s->Y5[r][2 * l];
                    // FSAL: next k1 = f(Y5) = k7, already in K[6]
                    *(float2*)&s->K[0][r][2 * l] = *(const float2*)&s->K[6][r][2 * l];
                }
            }
            float factor = 0.9f * powf(fmaxf(ratio, 1e-10f), -0.2f);
            factor = fminf(fmaxf(factor, 0.2f), 10.0f);
            dt = dt * factor;
            sc++;
            __syncwarp();
        }

        t = t_target;  // snap to target (matches reference)

        // write accepted state for this interval (coalesced)
        __syncwarp();
        #pragma unroll
        for (int rr = 0; rr < RPW; rr++) {
            const int r = r0 + rr;
            float2 v = *(const float2*)&s->Y[r][2 * l];
            *(float2*)&sol[((size_t)(row0 + r) * T_ + (ti + 1)) * D_ + 2 * l] = v;
        }
    }
}

// ---------------- decode kernel: pred = sol_z @ Wo + bo (R8 proven, pred-only) ----
#define DEC_ROWS 32
__global__ void __launch_bounds__(256)
decode_kernel(const float* __restrict__ gWo, const float* __restrict__ gbo,
              const float* __restrict__ sol_src, float* __restrict__ pred_out) {
    __shared__ float sWo[D_][O_];        // 32 KB
    __shared__ float sbo[O_];
    __shared__ float sx[DEC_ROWS][D_];   // 8 KB

    const int tid = threadIdx.x;
    for (int i = tid; i < D_ * O_; i += 256) ((float*)sWo)[i] = gWo[i];
    for (int i = tid; i < O_; i += 256) sbo[i] = gbo[i];

    const size_t row0 = (size_t)blockIdx.x * DEC_ROWS;
    for (int i = tid; i < DEC_ROWS * D_; i += 256)
        ((float*)sx)[i] = sol_src[row0 * D_ + i];
    __syncthreads();

    const int w = tid >> 5;
    const int l = tid & 31;
    const int rb = w * 4;                // 8 warps x 4 rows = 32 rows

    u64 a0[4], a1[4];
    {
        const u64* bop = (const u64*)sbo;
        u64 i0 = bop[2 * l], i1 = bop[2 * l + 1];
        #pragma unroll
        for (int rr = 0; rr < 4; rr++) { a0[rr] = i0; a1[rr] = i1; }
    }
    #pragma unroll 4
    for (int d0 = 0; d0 < D_; d0 += 4) {
        ulonglong2 wq[4];
        #pragma unroll
        for (int dd = 0; dd < 4; dd++)
            wq[dd] = *(const ulonglong2*)&sWo[d0 + dd][4 * l];
        float4 xv[4];
        #pragma unroll
        for (int rr = 0; rr < 4; rr++)
            xv[rr] = *(const float4*)&sx[rb + rr][d0];
        #pragma unroll
        for (int dd = 0; dd < 4; dd++) {
            #pragma unroll
            for (int rr = 0; rr < 4; rr++) {
                float x = (dd == 0) ? xv[rr].x : (dd == 1) ? xv[rr].y
                        : (dd == 2) ? xv[rr].z : xv[rr].w;
                u64 xd = dup2(x);
                a0[rr] = ffma2(xd, wq[dd].x, a0[rr]);
                a1[rr] = ffma2(xd, wq[dd].y, a1[rr]);
            }
        }
    }
    #pragma unroll
    for (int rr = 0; rr < 4; rr++) {
        const size_t r = row0 + rb + rr;
        float2 lo = u2f2(a0[rr]), hi = u2f2(a1[rr]);
        *(float4*)&pred_out[r * O_ + 4 * l] = make_float4(lo.x, lo.y, hi.x, hi.y);
    }
}

// ---------------- launch ----------------
extern "C" void kernel_launch(void* const* d_in, const int* in_sizes, int n_in,
                              void* d_out, int out_size) {
    const float* first_point = (const float*)d_in[0];
    const float* times       = (const float*)d_in[1];
    const float* W1          = (const float*)d_in[2];
    const float* b1          = (const float*)d_in[3];
    const float* W2          = (const float*)d_in[4];
    const float* b2          = (const float*)d_in[5];
    const float* Wo          = (const float*)d_in[6];
    const float* bo          = (const float*)d_in[7];

    float* out = (float*)d_out;
    const long long NS = (long long)NROW * T_ * D_;   // 12,582,912 (sol_z)
    const long long NP = (long long)NROW * T_ * O_;   // 25,165,824 (pred_x)

    float* sol_dst;
    float* pred_out;
    if ((long long)out_size == NS + NP)      { sol_dst = out;  pred_out = out + NS; }
    else if ((long long)out_size == NP) {
        float* gsol_ptr = nullptr;
        cudaGetSymbolAddress((void**)&gsol_ptr, g_sol);
        sol_dst = gsol_ptr; pred_out = out;
    }
    else if ((long long)out_size == NS)      { sol_dst = out;  pred_out = nullptr; }
    else                                     { sol_dst = out;  pred_out = out + NS; }

    cudaFuncSetAttribute(ode_kernel, cudaFuncAttributeMaxDynamicSharedMemorySize, SMEM_BYTES);

    ode_kernel<<<NCTA, TPB, SMEM_BYTES>>>(first_point, times, W1, b1, W2, b2, sol_dst);

    if (pred_out)
        decode_kernel<<<(NROW * T_) / DEC_ROWS, 256>>>(Wo, bo, sol_dst, pred_out);
}